// round 8
// baseline (speedup 1.0000x reference)
#include <cuda_runtime.h>
#include <math.h>
#include <stdint.h>

#define T 2048
#define H 2048
#define NH 32
#define NKV 8
#define HD 64
#define FFN 4096
#define NE 8
#define QKV_N 3072
#define ASSIGN (2*T)

// ---------------- scratch ----------------------------------------------------
__device__ float g_xnorm[T*H];
__device__ float g_qkv[(long)T*QKV_N];
__device__ float g_attn[(long)T*H];
__device__ float g_x2[(long)T*H];     // exact (router)
__device__ float g_x2r[(long)T*H];    // tf32-rounded (GEMM A)
__device__ float g_h1[(long)ASSIGN*FFN];
__device__ float g_h3[(long)ASSIGN*FFN];
__device__ float g_y[(long)ASSIGN*H];
__device__ int   g_counts[NE];
__device__ int   g_offs[NE];
__device__ int   g_fill[NE];
__device__ int   g_perm[ASSIGN];
__device__ float g_permw[ASSIGN];
__device__ int   g_tokpos[ASSIGN];
__device__ int   g_topid[T*2];
__device__ float g_topw[T*2];

// ---------------- helpers ------------------------------------------------------
__device__ __forceinline__ uint32_t f2tf(float f) {
    uint32_t u; asm("cvt.rna.tf32.f32 %0, %1;" : "=r"(u) : "f"(f)); return u;
}
__device__ __forceinline__ float f2tff(float f) { return __uint_as_float(f2tf(f)); }
__device__ __forceinline__ void mma_tf32(float* c, const uint32_t* a, const uint32_t* b) {
    asm volatile(
        "mma.sync.aligned.m16n8k8.row.col.f32.tf32.tf32.f32 "
        "{%0,%1,%2,%3},{%4,%5,%6,%7},{%8,%9},{%0,%1,%2,%3};"
        : "+f"(c[0]), "+f"(c[1]), "+f"(c[2]), "+f"(c[3])
        : "r"(a[0]), "r"(a[1]), "r"(a[2]), "r"(a[3]), "r"(b[0]), "r"(b[1]));
}
__device__ __forceinline__ uint32_t smem_u32(const void* p) {
    uint32_t a;
    asm("{ .reg .u64 t; cvta.to.shared.u64 t, %1; cvt.u32.u64 %0, t; }" : "=r"(a) : "l"(p));
    return a;
}
__device__ __forceinline__ void cpasync16(uint32_t dst, const void* src, int szBytes) {
    asm volatile("cp.async.cg.shared.global [%0], [%1], 16, %2;"
        :: "r"(dst), "l"(src), "r"(szBytes) : "memory");
}
__device__ __forceinline__ void cpasync_commit() {
    asm volatile("cp.async.commit_group;" ::: "memory");
}
template<int N>
__device__ __forceinline__ void cpasync_wait() {
    asm volatile("cp.async.wait_group %0;" :: "n"(N) : "memory");
}

// ---------------- rmsnorm (writes rounded out; optionally exact out2) ----------
__global__ __launch_bounds__(256) void rmsnorm_kernel(
    const float* __restrict__ x, const float* __restrict__ w,
    float* __restrict__ outR, float* __restrict__ outX)
{
    int t = blockIdx.x;
    const float* xr = x + (long)t*H;
    __shared__ float red[256];
    float s = 0.f;
    for (int h = threadIdx.x; h < H; h += 256) { float v = xr[h]; s += v*v; }
    red[threadIdx.x] = s; __syncthreads();
    for (int st = 128; st > 0; st >>= 1) {
        if (threadIdx.x < st) red[threadIdx.x] += red[threadIdx.x+st];
        __syncthreads();
    }
    float inv = rsqrtf(red[0]/(float)H + 1e-5f);
    for (int h = threadIdx.x; h < H; h += 256) {
        float v = xr[h]*inv*w[h];
        outR[(long)t*H + h] = f2tff(v);
        if (outX) outX[(long)t*H + h] = v;
    }
}

// ---------------- tf32 mma.sync GEMM: 128x256 CTA, 64x64 warp tiles ------------
// GRID: x = m-blocks (fastest -> consecutive CTAs share the same B slab in L2),
//       y = n-blocks, z = expert.
// A: pre-rounded fp32 (cp.async). B: RAW fp32 weights, rounded during staging.
// MODE 0: C = A@B (+addsrc). MODE 1: MoE up (A rows via g_perm).
// MODE 2: MoE down (A rows offs+r, scaled by g_permw).
#define AP6 36
#define BP6 264
#define A6_FLOATS (128*AP6)
#define B6_FLOATS (32*BP6)
#define G8_SMEM ((2*(A6_FLOATS+B6_FLOATS))*4)

template<int MODE>
__global__ __launch_bounds__(256) void gemm8(
    const float* __restrict__ A, const float* __restrict__ B, float* __restrict__ C,
    int M, int N, int K, const float* __restrict__ addsrc, long bStrideZ)
{
    extern __shared__ float sm8[];
    int z = blockIdx.z;
    int mBase = blockIdx.x * 128;     // m fastest
    int nBase = blockIdx.y * 256;
    int Meff = M, rowOff = 0;
    if (MODE == 1 || MODE == 2) {
        Meff = g_counts[z]; rowOff = g_offs[z];
        if (mBase >= Meff) return;
        B += (long)z * bStrideZ;
    }

    int tid = threadIdx.x, lane = tid & 31, wid = tid >> 5;
    int mW = (wid >> 2) * 64;
    int nW = (wid & 3) * 64;
    int g  = lane >> 2, t4 = lane & 3;

    uint32_t sAbase = smem_u32(sm8);
    float* sB = sm8 + 2*A6_FLOATS;

    // A staging: rows (tid>>3)+32i, 16B chunk (tid&7)
    int arow = tid >> 3;
    int ac   = tid & 7;
    const float* aPtr[4]; int aSz[4];
    #pragma unroll
    for (int i = 0; i < 4; i++) {
        int gm = mBase + arow + 32*i;
        bool ok = gm < Meff;
        long r;
        if (MODE == 1)      r = ok ? (long)g_perm[rowOff + gm] : 0;
        else if (MODE == 2) r = (long)(rowOff + (ok ? gm : 0));
        else                r = (long)(ok ? gm : 0);
        aPtr[i] = A + r*(long)K + ac*4;
        aSz[i]  = ok ? 16 : 0;
    }
    // B staging: k-rows (tid>>6)+4i (i<8), 16B chunk (tid&63)
    int bkk = tid >> 6;
    int bc  = tid & 63;
    const float* bPtr = B + (long)bkk*N + nBase + bc*4;

    float acc[4][8][4];
    #pragma unroll
    for (int mt = 0; mt < 4; mt++)
        #pragma unroll
        for (int nt = 0; nt < 8; nt++)
            #pragma unroll
            for (int q = 0; q < 4; q++) acc[mt][nt][q] = 0.f;

    int KT = K >> 5;
    float4 bR[8];

    // ---- prologue: stage k-tile 0 ----
    #pragma unroll
    for (int i = 0; i < 4; i++)
        cpasync16(sAbase + ((arow + 32*i)*AP6 + ac*4)*4u, aPtr[i], aSz[i]);
    cpasync_commit();
    #pragma unroll
    for (int i = 0; i < 8; i++)
        bR[i] = *(const float4*)(bPtr + (long)(4*i)*N);
    {
        float* d = sB;   // buf 0
        #pragma unroll
        for (int i = 0; i < 8; i++) {
            uint4 u = { f2tf(bR[i].x), f2tf(bR[i].y), f2tf(bR[i].z), f2tf(bR[i].w) };
            *(uint4*)(d + (bkk + 4*i)*BP6 + bc*4) = u;
        }
    }
    cpasync_wait<0>();
    __syncthreads();

    for (int kt = 0; kt < KT; kt++) {
        int buf = kt & 1;
        int nb  = buf ^ 1;
        if (kt + 1 < KT) {
            int k0 = (kt + 1) << 5;
            uint32_t aD = sAbase + (uint32_t)nb*A6_FLOATS*4u;
            #pragma unroll
            for (int i = 0; i < 4; i++)
                cpasync16(aD + ((arow + 32*i)*AP6 + ac*4)*4u, aPtr[i] + k0, aSz[i]);
            cpasync_commit();
            #pragma unroll
            for (int i = 0; i < 8; i++)
                bR[i] = *(const float4*)(bPtr + (long)(k0 + 4*i)*N);
        }

        const uint32_t* as = (const uint32_t*)(sm8 + buf*A6_FLOATS);
        const uint32_t* bs = (const uint32_t*)(sB + buf*B6_FLOATS);

        #pragma unroll
        for (int s = 0; s < 4; s++) {
            uint32_t af[4][4], bf[8][2];
            #pragma unroll
            for (int mt = 0; mt < 4; mt++) {
                const uint32_t* p = as + (mW + mt*16 + g)*AP6 + s*8 + t4;
                af[mt][0] = p[0];
                af[mt][1] = p[8*AP6];
                af[mt][2] = p[4];
                af[mt][3] = p[8*AP6 + 4];
            }
            #pragma unroll
            for (int nt = 0; nt < 8; nt++) {
                const uint32_t* p = bs + (s*8 + t4)*BP6 + nW + nt*8 + g;
                bf[nt][0] = p[0];
                bf[nt][1] = p[4*BP6];
            }
            #pragma unroll
            for (int mt = 0; mt < 4; mt++)
                #pragma unroll
                for (int nt = 0; nt < 8; nt++)
                    mma_tf32(acc[mt][nt], af[mt], bf[nt]);
        }

        if (kt + 1 < KT) {
            float* d = sB + nb*B6_FLOATS;
            #pragma unroll
            for (int i = 0; i < 8; i++) {
                uint4 u = { f2tf(bR[i].x), f2tf(bR[i].y), f2tf(bR[i].z), f2tf(bR[i].w) };
                *(uint4*)(d + (bkk + 4*i)*BP6 + bc*4) = u;
            }
            cpasync_wait<0>();
        }
        __syncthreads();
    }

    // ---- epilogue ----
    #pragma unroll
    for (int mt = 0; mt < 4; mt++) {
        #pragma unroll
        for (int half = 0; half < 2; half++) {
            int rRel = mW + mt*16 + g + half*8;
            bool ok = (MODE == 0) || (mBase + rRel < Meff);
            if (!ok) continue;
            long crow;
            float scale = 1.f;
            if (MODE == 0) crow = (long)(mBase + rRel);
            else           crow = (long)(rowOff + mBase + rRel);
            if (MODE == 2) scale = g_permw[rowOff + mBase + rRel];
            #pragma unroll
            for (int nt = 0; nt < 8; nt++) {
                int col = nBase + nW + nt*8 + t4*2;
                float v0 = acc[mt][nt][2*half + 0];
                float v1 = acc[mt][nt][2*half + 1];
                if (MODE == 2) { v0 *= scale; v1 *= scale; }
                if (MODE == 0 && addsrc) {
                    v0 += addsrc[crow*N + col];
                    v1 += addsrc[crow*N + col + 1];
                }
                *(float2*)(C + crow*N + col) = make_float2(v0, v1);
            }
        }
    }
}

// ---------------- RoPE --------------------------------------------------------
__global__ __launch_bounds__(256) void rope_kernel(float* __restrict__ qkv)
{
    int t = blockIdx.x;
    float pos = (float)t;
    for (int idx = threadIdx.x; idx < (NH+NKV)*32; idx += 256) {
        int head = idx >> 5;
        int j    = idx & 31;
        int colbase = (head < NH) ? head*HD : (NH*HD + (head-NH)*HD);
        float inv = expf(-((float)(2*j)/(float)HD) * logf(10000.0f));
        float f = pos * inv;
        float c = cosf(f), sn = sinf(f);
        float* p = qkv + (long)t*QKV_N + colbase;
        float x1 = p[j], x2 = p[j+32];
        p[j]    = x1*c - x2*sn;
        p[j+32] = x2*c + x1*sn;
    }
}

// ---------------- tensor-core flash attention (mma.sync) -----------------------
#define AP 68
#define ATTN_SMEM (6*64*AP*4)

__global__ __launch_bounds__(128) void attn_tc_kernel(
    const float* __restrict__ qkv, float* __restrict__ attn)
{
    extern __shared__ uint32_t su[];
    uint32_t* sQh = su;
    uint32_t* sQl = sQh + 64*AP;
    uint32_t* sKh = sQl + 64*AP;
    uint32_t* sKl = sKh + 64*AP;
    uint32_t* sV  = sKl + 64*AP;
    uint32_t* sP  = sV  + 64*AP;

    int h = blockIdx.y, qt = blockIdx.x;
    int kvh = h >> 2;
    int tid = threadIdx.x, lane = tid & 31, w = tid >> 5;
    int g = lane >> 2, t4 = lane & 3;
    int mRow = w*16 + g;

    for (int i = tid; i < 1024; i += 128) {
        int r = i >> 4, d4 = (i & 15) << 2;
        float4 v = *(const float4*)(qkv + (long)(qt*64 + r)*QKV_N + h*HD + d4);
        float vv[4] = {v.x*0.125f, v.y*0.125f, v.z*0.125f, v.w*0.125f};
        #pragma unroll
        for (int j = 0; j < 4; j++) {
            uint32_t hi = f2tf(vv[j]);
            float lo = vv[j] - __uint_as_float(hi);
            sQh[r*AP + d4 + j] = hi;
            sQl[r*AP + d4 + j] = f2tf(lo);
        }
    }

    float m_a = -1e30f, m_b = -1e30f, l_a = 0.f, l_b = 0.f;
    float o[8][4];
    #pragma unroll
    for (int nt = 0; nt < 8; nt++)
        #pragma unroll
        for (int q = 0; q < 4; q++) o[nt][q] = 0.f;

    for (int kt = 0; kt <= qt; kt++) {
        __syncthreads();
        for (int i = tid; i < 1024; i += 128) {
            int r = i >> 4, d4 = (i & 15) << 2;
            const float* kp = qkv + (long)(kt*64 + r)*QKV_N + NH*HD + kvh*HD + d4;
            float4 kv = *(const float4*)kp;
            float4 vv = *(const float4*)(kp + NKV*HD);
            float kk[4] = {kv.x, kv.y, kv.z, kv.w};
            float vf[4] = {vv.x, vv.y, vv.z, vv.w};
            #pragma unroll
            for (int j = 0; j < 4; j++) {
                uint32_t hi = f2tf(kk[j]);
                float lo = kk[j] - __uint_as_float(hi);
                sKh[r*AP + d4 + j] = hi;
                sKl[r*AP + d4 + j] = f2tf(lo);
                sV [r*AP + d4 + j] = f2tf(vf[j]);
            }
        }
        __syncthreads();

        float s[8][4];
        #pragma unroll
        for (int nt = 0; nt < 8; nt++)
            #pragma unroll
            for (int q = 0; q < 4; q++) s[nt][q] = 0.f;

        #pragma unroll
        for (int ks = 0; ks < 8; ks++) {
            uint32_t ah[4], al[4];
            {
                const uint32_t* p = sQh + mRow*AP + ks*8 + t4;
                ah[0]=p[0]; ah[1]=p[8*AP]; ah[2]=p[4]; ah[3]=p[8*AP+4];
                const uint32_t* q2 = sQl + mRow*AP + ks*8 + t4;
                al[0]=q2[0]; al[1]=q2[8*AP]; al[2]=q2[4]; al[3]=q2[8*AP+4];
            }
            #pragma unroll
            for (int nt = 0; nt < 8; nt++) {
                uint32_t bh[2], bl[2];
                const uint32_t* p = sKh + (nt*8 + g)*AP + ks*8 + t4;
                bh[0] = p[0]; bh[1] = p[4];
                const uint32_t* q2 = sKl + (nt*8 + g)*AP + ks*8 + t4;
                bl[0] = q2[0]; bl[1] = q2[4];
                mma_tf32(s[nt], ah, bh);
                mma_tf32(s[nt], ah, bl);
                mma_tf32(s[nt], al, bh);
            }
        }

        if (kt == qt) {
            #pragma unroll
            for (int nt = 0; nt < 8; nt++) {
                int c0 = nt*8 + 2*t4;
                if (c0     > mRow)   s[nt][0] = -1e30f;
                if (c0 + 1 > mRow)   s[nt][1] = -1e30f;
                if (c0     > mRow+8) s[nt][2] = -1e30f;
                if (c0 + 1 > mRow+8) s[nt][3] = -1e30f;
            }
        }

        float rma = -1e30f, rmb = -1e30f;
        #pragma unroll
        for (int nt = 0; nt < 8; nt++) {
            rma = fmaxf(rma, fmaxf(s[nt][0], s[nt][1]));
            rmb = fmaxf(rmb, fmaxf(s[nt][2], s[nt][3]));
        }
        rma = fmaxf(rma, __shfl_xor_sync(0xffffffffu, rma, 1));
        rma = fmaxf(rma, __shfl_xor_sync(0xffffffffu, rma, 2));
        rmb = fmaxf(rmb, __shfl_xor_sync(0xffffffffu, rmb, 1));
        rmb = fmaxf(rmb, __shfl_xor_sync(0xffffffffu, rmb, 2));

        float mna = fmaxf(m_a, rma), mnb = fmaxf(m_b, rmb);
        float suma = 0.f, sumb = 0.f;
        #pragma unroll
        for (int nt = 0; nt < 8; nt++) {
            s[nt][0] = __expf(s[nt][0] - mna); suma += s[nt][0];
            s[nt][1] = __expf(s[nt][1] - mna); suma += s[nt][1];
            s[nt][2] = __expf(s[nt][2] - mnb); sumb += s[nt][2];
            s[nt][3] = __expf(s[nt][3] - mnb); sumb += s[nt][3];
        }
        suma += __shfl_xor_sync(0xffffffffu, suma, 1);
        suma += __shfl_xor_sync(0xffffffffu, suma, 2);
        sumb += __shfl_xor_sync(0xffffffffu, sumb, 1);
        sumb += __shfl_xor_sync(0xffffffffu, sumb, 2);

        float alpa = __expf(m_a - mna), alpb = __expf(m_b - mnb);
        l_a = l_a*alpa + suma; m_a = mna;
        l_b = l_b*alpb + sumb; m_b = mnb;
        #pragma unroll
        for (int nt = 0; nt < 8; nt++) {
            o[nt][0] *= alpa; o[nt][1] *= alpa;
            o[nt][2] *= alpb; o[nt][3] *= alpb;
        }

        #pragma unroll
        for (int nt = 0; nt < 8; nt++) {
            int c0 = nt*8 + 2*t4;
            sP[mRow*AP + c0]       = f2tf(s[nt][0]);
            sP[mRow*AP + c0 + 1]   = f2tf(s[nt][1]);
            sP[(mRow+8)*AP + c0]   = f2tf(s[nt][2]);
            sP[(mRow+8)*AP + c0+1] = f2tf(s[nt][3]);
        }
        __syncwarp();

        #pragma unroll
        for (int ks = 0; ks < 8; ks++) {
            uint32_t ap[4];
            const uint32_t* p = sP + mRow*AP + ks*8 + t4;
            ap[0]=p[0]; ap[1]=p[8*AP]; ap[2]=p[4]; ap[3]=p[8*AP+4];
            #pragma unroll
            for (int nt = 0; nt < 8; nt++) {
                uint32_t bv[2];
                bv[0] = sV[(ks*8 + t4)*AP + nt*8 + g];
                bv[1] = sV[(ks*8 + t4 + 4)*AP + nt*8 + g];
                mma_tf32(o[nt], ap, bv);
            }
        }
    }

    float inva = 1.f / l_a, invb = 1.f / l_b;
    #pragma unroll
    for (int nt = 0; nt < 8; nt++) {
        int col = h*HD + nt*8 + 2*t4;
        long ra = (long)(qt*64 + mRow);
        *(float2*)(attn + ra*H + col) =
            make_float2(f2tff(o[nt][0]*inva), f2tff(o[nt][1]*inva));
        *(float2*)(attn + (ra+8)*H + col) =
            make_float2(f2tff(o[nt][2]*invb), f2tff(o[nt][3]*invb));
    }
}

// ---------------- router / MoE plumbing ---------------------------------------
__global__ void reset_kernel() { if (threadIdx.x < NE) g_counts[threadIdx.x] = 0; }

__global__ __launch_bounds__(256) void router_kernel(
    const float* __restrict__ x, const float* __restrict__ gw)
{
    int t = blockIdx.x;
    const float* xr = x + (long)t*H;
    float p[NE] = {};
    for (int h = threadIdx.x; h < H; h += 256) {
        float xv = xr[h];
        #pragma unroll
        for (int e = 0; e < NE; e++) p[e] += xv * gw[h*NE + e];
    }
    __shared__ float red[NE*256];
    #pragma unroll
    for (int e = 0; e < NE; e++) red[e*256 + threadIdx.x] = p[e];
    __syncthreads();
    for (int st = 128; st > 0; st >>= 1) {
        if (threadIdx.x < st)
            #pragma unroll
            for (int e = 0; e < NE; e++)
                red[e*256+threadIdx.x] += red[e*256+threadIdx.x+st];
        __syncthreads();
    }
    if (threadIdx.x == 0) {
        float l[NE];
        #pragma unroll
        for (int e = 0; e < NE; e++) l[e] = red[e*256];
        int i1 = 0;
        #pragma unroll
        for (int e = 1; e < NE; e++) if (l[e] > l[i1]) i1 = e;
        int i2 = -1;
        #pragma unroll
        for (int e = 0; e < NE; e++) if (e != i1 && (i2 < 0 || l[e] > l[i2])) i2 = e;
        float p2 = expf(l[i2] - l[i1]);
        float inv = 1.f / (1.f + p2);
        g_topid[2*t] = i1;   g_topid[2*t+1] = i2;
        g_topw[2*t]  = inv;  g_topw[2*t+1]  = p2*inv;
        atomicAdd(&g_counts[i1], 1);
        atomicAdd(&g_counts[i2], 1);
    }
}

__global__ void scan_kernel() {
    if (threadIdx.x == 0) {
        int s = 0;
        for (int e = 0; e < NE; e++) { g_offs[e] = s; g_fill[e] = s; s += g_counts[e]; }
    }
}

__global__ void scatter_kernel() {
    int t = blockIdx.x*256 + threadIdx.x;
    if (t >= T) return;
    #pragma unroll
    for (int k = 0; k < 2; k++) {
        int e = g_topid[2*t+k];
        int pos = atomicAdd(&g_fill[e], 1);
        g_perm[pos]  = t;
        g_permw[pos] = g_topw[2*t+k];
        g_tokpos[2*t+k] = pos;
    }
}

__global__ __launch_bounds__(256) void silu_kernel() {
    long n = (long)ASSIGN*FFN;
    for (long i = (long)blockIdx.x*256 + threadIdx.x; i < n; i += (long)gridDim.x*256) {
        float a = g_h1[i];
        g_h1[i] = f2tff((a / (1.f + expf(-a))) * g_h3[i]);
    }
}

__global__ __launch_bounds__(256) void combine_kernel(float* __restrict__ out) {
    int idx = blockIdx.x*256 + threadIdx.x;
    int t = idx >> 11;
    int c = idx & (H-1);
    out[idx] = g_y[(long)g_tokpos[2*t]*H + c] + g_y[(long)g_tokpos[2*t+1]*H + c];
}

// ---------------- launch --------------------------------------------------------
extern "C" void kernel_launch(void* const* d_in, const int* in_sizes, int n_in,
                              void* d_out, int out_size)
{
    const float* hidden = (const float*)d_in[0];
    const float* w_qkv  = (const float*)d_in[2];
    const float* w_o    = (const float*)d_in[3];
    const float* gate_w = (const float*)d_in[4];
    const float* w1     = (const float*)d_in[5];
    const float* w2     = (const float*)d_in[6];
    const float* w3     = (const float*)d_in[7];
    const float* ln1    = (const float*)d_in[8];
    const float* ln2    = (const float*)d_in[9];

    float* out       = (float*)d_out;
    float* final_out = out;
    float* resid_out = out + (long)T*H;

    float *xnorm, *qkvb, *attnb, *x2, *x2r, *h1, *h3, *y;
    cudaGetSymbolAddress((void**)&xnorm, g_xnorm);
    cudaGetSymbolAddress((void**)&qkvb,  g_qkv);
    cudaGetSymbolAddress((void**)&attnb, g_attn);
    cudaGetSymbolAddress((void**)&x2,    g_x2);
    cudaGetSymbolAddress((void**)&x2r,   g_x2r);
    cudaGetSymbolAddress((void**)&h1,    g_h1);
    cudaGetSymbolAddress((void**)&h3,    g_h3);
    cudaGetSymbolAddress((void**)&y,     g_y);

    static bool attrDone = false;
    if (!attrDone) {
        cudaFuncSetAttribute(gemm8<0>, cudaFuncAttributeMaxDynamicSharedMemorySize, G8_SMEM);
        cudaFuncSetAttribute(gemm8<1>, cudaFuncAttributeMaxDynamicSharedMemorySize, G8_SMEM);
        cudaFuncSetAttribute(gemm8<2>, cudaFuncAttributeMaxDynamicSharedMemorySize, G8_SMEM);
        cudaFuncSetAttribute(attn_tc_kernel, cudaFuncAttributeMaxDynamicSharedMemorySize, ATTN_SMEM);
        attrDone = true;
    }

    // ---- attention path ----
    rmsnorm_kernel<<<T,256>>>(hidden, ln1, xnorm, nullptr);
    {
        dim3 g(T/128, QKV_N/256, 1);      // m fastest
        gemm8<0><<<g,256,G8_SMEM>>>(xnorm, w_qkv, qkvb, T, QKV_N, H, nullptr, 0);
    }
    rope_kernel<<<T,256>>>(qkvb);
    {
        dim3 g(T/64, NH, 1);
        attn_tc_kernel<<<g,128,ATTN_SMEM>>>(qkvb, attnb);
    }
    {
        dim3 g(T/128, H/256, 1);          // m fastest
        gemm8<0><<<g,256,G8_SMEM>>>(attnb, w_o, resid_out, T, H, H, hidden, 0);
    }

    // ---- MoE path ----
    rmsnorm_kernel<<<T,256>>>(resid_out, ln2, x2r, x2);
    reset_kernel<<<1,32>>>();
    router_kernel<<<T,256>>>(x2, gate_w);
    scan_kernel<<<1,1>>>();
    scatter_kernel<<<(T+255)/256,256>>>();
    {
        dim3 g(T/128, FFN/256, NE);       // m fastest
        gemm8<1><<<g,256,G8_SMEM>>>(x2r, w1, h1, T, FFN, H, nullptr, (long)H*FFN);
        gemm8<1><<<g,256,G8_SMEM>>>(x2r, w3, h3, T, FFN, H, nullptr, (long)H*FFN);
    }
    silu_kernel<<<4096,256>>>();
    {
        dim3 g(T/128, H/256, NE);         // m fastest
        gemm8<2><<<g,256,G8_SMEM>>>(h1, w2, y, T, H, FFN, nullptr, (long)FFN*H);
    }
    combine_kernel<<<(T*H)/256,256>>>(final_out);
}

// round 9
// speedup vs baseline: 1.2860x; 1.2860x over previous
#include <cuda_runtime.h>
#include <cuda_fp16.h>
#include <math.h>
#include <stdint.h>

#define T 2048
#define H 2048
#define NH 32
#define NKV 8
#define HD 64
#define FFN 4096
#define NE 8
#define QKV_N 3072
#define ASSIGN (2*T)

// ---------------- scratch ----------------------------------------------------
__device__ float g_xnorm[T*H];
__device__ float g_qkv[(long)T*QKV_N];
__device__ float g_attn[(long)T*H];
__device__ float g_x2[(long)T*H];
__device__ float g_h1[(long)ASSIGN*FFN];
__device__ float g_h3[(long)ASSIGN*FFN];
__device__ float g_y[(long)ASSIGN*H];
__device__ int   g_counts[NE];
__device__ int   g_offs[NE];
__device__ int   g_fill[NE];
__device__ int   g_perm[ASSIGN];
__device__ float g_permw[ASSIGN];
__device__ int   g_tokpos[ASSIGN];
__device__ int   g_topid[T*2];
__device__ float g_topw[T*2];

// ---------------- helpers ------------------------------------------------------
__device__ __forceinline__ uint32_t f2tf(float f) {
    uint32_t u; asm("cvt.rna.tf32.f32 %0, %1;" : "=r"(u) : "f"(f)); return u;
}
__device__ __forceinline__ void mma_tf32(float* c, const uint32_t* a, const uint32_t* b) {
    asm volatile(
        "mma.sync.aligned.m16n8k8.row.col.f32.tf32.tf32.f32 "
        "{%0,%1,%2,%3},{%4,%5,%6,%7},{%8,%9},{%0,%1,%2,%3};"
        : "+f"(c[0]), "+f"(c[1]), "+f"(c[2]), "+f"(c[3])
        : "r"(a[0]), "r"(a[1]), "r"(a[2]), "r"(a[3]), "r"(b[0]), "r"(b[1]));
}
__device__ __forceinline__ void mma_f16(float* c, const uint32_t* a, const uint32_t* b) {
    asm volatile(
        "mma.sync.aligned.m16n8k16.row.col.f32.f16.f16.f32 "
        "{%0,%1,%2,%3},{%4,%5,%6,%7},{%8,%9},{%0,%1,%2,%3};"
        : "+f"(c[0]), "+f"(c[1]), "+f"(c[2]), "+f"(c[3])
        : "r"(a[0]), "r"(a[1]), "r"(a[2]), "r"(a[3]), "r"(b[0]), "r"(b[1]));
}
__device__ __forceinline__ uint32_t packh2(float lo, float hi) {
    __half2 h = __floats2half2_rn(lo, hi);
    return *(uint32_t*)&h;
}
__device__ __forceinline__ uint32_t smem_u32(const void* p) {
    uint32_t a;
    asm("{ .reg .u64 t; cvta.to.shared.u64 t, %1; cvt.u32.u64 %0, t; }" : "=r"(a) : "l"(p));
    return a;
}

// ---------------- rmsnorm ------------------------------------------------------
__global__ __launch_bounds__(256) void rmsnorm_kernel(
    const float* __restrict__ x, const float* __restrict__ w, float* __restrict__ out)
{
    int t = blockIdx.x;
    const float* xr = x + (long)t*H;
    __shared__ float red[256];
    float s = 0.f;
    for (int h = threadIdx.x; h < H; h += 256) { float v = xr[h]; s += v*v; }
    red[threadIdx.x] = s; __syncthreads();
    for (int st = 128; st > 0; st >>= 1) {
        if (threadIdx.x < st) red[threadIdx.x] += red[threadIdx.x+st];
        __syncthreads();
    }
    float inv = rsqrtf(red[0]/(float)H + 1e-5f);
    float* orow = out + (long)t*H;
    for (int h = threadIdx.x; h < H; h += 256) orow[h] = xr[h]*inv*w[h];
}

// ---------------- fp16 mma.sync GEMM: 128x256 CTA, 64x64 warp tiles ------------
// A [m][k] fp32, B [k][n] fp32 (raw) -- both converted to fp16 during staging.
// B is stored [n][k-pair] in smem so fragments are k-contiguous (row.col MMA).
// MODE 0: C = A@B (+addsrc). MODE 1: MoE up (A rows via g_perm).
// MODE 2: MoE down (A rows offs+r, scaled by g_permw).
#define PAW 18                    // 32-bit words per A smem row (16 used + 2 pad)
#define PBW 18                    // words per B smem row
#define A9_WORDS (128*PAW)
#define B9_WORDS (256*PBW)
#define G9_SMEM ((2*(A9_WORDS+B9_WORDS))*4)

template<int MODE>
__global__ __launch_bounds__(256) void gemm9(
    const float* __restrict__ A, const float* __restrict__ B, float* __restrict__ C,
    int M, int N, int K, const float* __restrict__ addsrc, long bStrideZ)
{
    extern __shared__ uint32_t sm9[];
    int z = blockIdx.z;
    int mBase = blockIdx.y * 128;
    int nBase = blockIdx.x * 256;
    int Meff = M, rowOff = 0;
    if (MODE == 1 || MODE == 2) {
        Meff = g_counts[z]; rowOff = g_offs[z];
        if (mBase >= Meff) return;
        B += (long)z * bStrideZ;
    }

    int tid = threadIdx.x, lane = tid & 31, wid = tid >> 5;
    int mW = (wid >> 2) * 64;
    int nW = (wid & 3) * 64;
    int g  = lane >> 2, t4 = lane & 3;

    uint32_t* smA = sm9;
    uint32_t* smB = sm9 + 2*A9_WORDS;

    // ---- A staging ids: row (tid>>3)+32i, float4 chunk (tid&7) ----
    int arow = tid >> 3;
    int ac   = tid & 7;
    const float* aPtr[4]; bool aOk[4];
    #pragma unroll
    for (int i = 0; i < 4; i++) {
        int gm = mBase + arow + 32*i;
        aOk[i] = gm < Meff;
        long r;
        if (MODE == 1)      r = aOk[i] ? (long)g_perm[rowOff + gm] : 0;
        else if (MODE == 2) r = (long)(rowOff + (aOk[i] ? gm : 0));
        else                r = (long)(aOk[i] ? gm : 0);
        aPtr[i] = A + r*(long)K + ac*4;
    }
    // ---- B staging ids: n = (tid&63) + 64j, k-pair = (tid>>6) + 4p ----
    int nl = tid & 63;
    int kp = tid >> 6;
    const float* bPtr = B + nBase + nl;

    float acc[4][8][4];
    #pragma unroll
    for (int mt = 0; mt < 4; mt++)
        #pragma unroll
        for (int nt = 0; nt < 8; nt++)
            #pragma unroll
            for (int q = 0; q < 4; q++) acc[mt][nt][q] = 0.f;

    int KT = K >> 5;
    float4 aR[4];
    float bv0[4][4], bv1[4][4];

    // ---- prologue: load + stage k-tile 0 ----
    #pragma unroll
    for (int i = 0; i < 4; i++)
        aR[i] = aOk[i] ? *(const float4*)(aPtr[i]) : make_float4(0.f,0.f,0.f,0.f);
    #pragma unroll
    for (int p = 0; p < 4; p++)
        #pragma unroll
        for (int j = 0; j < 4; j++) {
            long ko = (long)(2*(kp + 4*p))*N + 64*j;
            bv0[p][j] = bPtr[ko];
            bv1[p][j] = bPtr[ko + N];
        }
    #pragma unroll
    for (int i = 0; i < 4; i++) {
        uint2 u = { packh2(aR[i].x, aR[i].y), packh2(aR[i].z, aR[i].w) };
        *(uint2*)(smA + (arow + 32*i)*PAW + ac*2) = u;
    }
    #pragma unroll
    for (int p = 0; p < 4; p++)
        #pragma unroll
        for (int j = 0; j < 4; j++)
            smB[(nl + 64*j)*PBW + kp + 4*p] = packh2(bv0[p][j], bv1[p][j]);
    __syncthreads();

    for (int kt = 0; kt < KT; kt++) {
        int buf = kt & 1;
        int nb  = buf ^ 1;
        if (kt + 1 < KT) {
            int k0 = (kt + 1) << 5;
            #pragma unroll
            for (int i = 0; i < 4; i++)
                aR[i] = aOk[i] ? *(const float4*)(aPtr[i] + k0)
                               : make_float4(0.f,0.f,0.f,0.f);
            #pragma unroll
            for (int p = 0; p < 4; p++)
                #pragma unroll
                for (int j = 0; j < 4; j++) {
                    long ko = (long)(k0 + 2*(kp + 4*p))*N + 64*j;
                    bv0[p][j] = bPtr[ko];
                    bv1[p][j] = bPtr[ko + N];
                }
        }

        const uint32_t* as = smA + buf*A9_WORDS;
        const uint32_t* bs = smB + buf*B9_WORDS;

        #pragma unroll
        for (int s = 0; s < 2; s++) {
            uint32_t af[4][4], bf[8][2];
            #pragma unroll
            for (int mt = 0; mt < 4; mt++) {
                const uint32_t* p = as + (mW + mt*16 + g)*PAW + s*8 + t4;
                af[mt][0] = p[0];
                af[mt][1] = p[8*PAW];
                af[mt][2] = p[4];
                af[mt][3] = p[8*PAW + 4];
            }
            #pragma unroll
            for (int nt = 0; nt < 8; nt++) {
                const uint32_t* p = bs + (nW + nt*8 + g)*PBW + s*8 + t4;
                bf[nt][0] = p[0];
                bf[nt][1] = p[4];
            }
            #pragma unroll
            for (int mt = 0; mt < 4; mt++)
                #pragma unroll
                for (int nt = 0; nt < 8; nt++)
                    mma_f16(acc[mt][nt], af[mt], bf[nt]);
        }

        if (kt + 1 < KT) {
            uint32_t* dA = smA + nb*A9_WORDS;
            uint32_t* dB = smB + nb*B9_WORDS;
            #pragma unroll
            for (int i = 0; i < 4; i++) {
                uint2 u = { packh2(aR[i].x, aR[i].y), packh2(aR[i].z, aR[i].w) };
                *(uint2*)(dA + (arow + 32*i)*PAW + ac*2) = u;
            }
            #pragma unroll
            for (int p = 0; p < 4; p++)
                #pragma unroll
                for (int j = 0; j < 4; j++)
                    dB[(nl + 64*j)*PBW + kp + 4*p] = packh2(bv0[p][j], bv1[p][j]);
        }
        __syncthreads();
    }

    // ---- epilogue ----
    #pragma unroll
    for (int mt = 0; mt < 4; mt++) {
        #pragma unroll
        for (int half = 0; half < 2; half++) {
            int rRel = mW + mt*16 + g + half*8;
            bool ok = (MODE == 0) || (mBase + rRel < Meff);
            if (!ok) continue;
            long crow;
            float scale = 1.f;
            if (MODE == 0) crow = (long)(mBase + rRel);
            else           crow = (long)(rowOff + mBase + rRel);
            if (MODE == 2) scale = g_permw[rowOff + mBase + rRel];
            #pragma unroll
            for (int nt = 0; nt < 8; nt++) {
                int col = nBase + nW + nt*8 + t4*2;
                float v0 = acc[mt][nt][2*half + 0];
                float v1 = acc[mt][nt][2*half + 1];
                if (MODE == 2) { v0 *= scale; v1 *= scale; }
                if (MODE == 0 && addsrc) {
                    v0 += addsrc[crow*N + col];
                    v1 += addsrc[crow*N + col + 1];
                }
                *(float2*)(C + crow*N + col) = make_float2(v0, v1);
            }
        }
    }
}

// ---------------- RoPE --------------------------------------------------------
__global__ __launch_bounds__(256) void rope_kernel(float* __restrict__ qkv)
{
    int t = blockIdx.x;
    float pos = (float)t;
    for (int idx = threadIdx.x; idx < (NH+NKV)*32; idx += 256) {
        int head = idx >> 5;
        int j    = idx & 31;
        int colbase = (head < NH) ? head*HD : (NH*HD + (head-NH)*HD);
        float inv = expf(-((float)(2*j)/(float)HD) * logf(10000.0f));
        float f = pos * inv;
        float c = cosf(f), sn = sinf(f);
        float* p = qkv + (long)t*QKV_N + colbase;
        float x1 = p[j], x2 = p[j+32];
        p[j]    = x1*c - x2*sn;
        p[j+32] = x2*c + x1*sn;
    }
}

// ---------------- tensor-core flash attention (split-tf32 mma.sync) ------------
#define AP 68
#define ATTN_SMEM (6*64*AP*4)

__global__ __launch_bounds__(128) void attn_tc_kernel(
    const float* __restrict__ qkv, float* __restrict__ attn)
{
    extern __shared__ uint32_t su[];
    uint32_t* sQh = su;
    uint32_t* sQl = sQh + 64*AP;
    uint32_t* sKh = sQl + 64*AP;
    uint32_t* sKl = sKh + 64*AP;
    uint32_t* sV  = sKl + 64*AP;
    uint32_t* sP  = sV  + 64*AP;

    int h = blockIdx.y, qt = blockIdx.x;
    int kvh = h >> 2;
    int tid = threadIdx.x, lane = tid & 31, w = tid >> 5;
    int g = lane >> 2, t4 = lane & 3;
    int mRow = w*16 + g;

    for (int i = tid; i < 1024; i += 128) {
        int r = i >> 4, d4 = (i & 15) << 2;
        float4 v = *(const float4*)(qkv + (long)(qt*64 + r)*QKV_N + h*HD + d4);
        float vv[4] = {v.x*0.125f, v.y*0.125f, v.z*0.125f, v.w*0.125f};
        #pragma unroll
        for (int j = 0; j < 4; j++) {
            uint32_t hi = f2tf(vv[j]);
            float lo = vv[j] - __uint_as_float(hi);
            sQh[r*AP + d4 + j] = hi;
            sQl[r*AP + d4 + j] = f2tf(lo);
        }
    }

    float m_a = -1e30f, m_b = -1e30f, l_a = 0.f, l_b = 0.f;
    float o[8][4];
    #pragma unroll
    for (int nt = 0; nt < 8; nt++)
        #pragma unroll
        for (int q = 0; q < 4; q++) o[nt][q] = 0.f;

    for (int kt = 0; kt <= qt; kt++) {
        __syncthreads();
        for (int i = tid; i < 1024; i += 128) {
            int r = i >> 4, d4 = (i & 15) << 2;
            const float* kp = qkv + (long)(kt*64 + r)*QKV_N + NH*HD + kvh*HD + d4;
            float4 kv = *(const float4*)kp;
            float4 vv = *(const float4*)(kp + NKV*HD);
            float kk[4] = {kv.x, kv.y, kv.z, kv.w};
            float vf[4] = {vv.x, vv.y, vv.z, vv.w};
            #pragma unroll
            for (int j = 0; j < 4; j++) {
                uint32_t hi = f2tf(kk[j]);
                float lo = kk[j] - __uint_as_float(hi);
                sKh[r*AP + d4 + j] = hi;
                sKl[r*AP + d4 + j] = f2tf(lo);
                sV [r*AP + d4 + j] = f2tf(vf[j]);
            }
        }
        __syncthreads();

        float s[8][4];
        #pragma unroll
        for (int nt = 0; nt < 8; nt++)
            #pragma unroll
            for (int q = 0; q < 4; q++) s[nt][q] = 0.f;

        #pragma unroll
        for (int ks = 0; ks < 8; ks++) {
            uint32_t ah[4], al[4];
            {
                const uint32_t* p = sQh + mRow*AP + ks*8 + t4;
                ah[0]=p[0]; ah[1]=p[8*AP]; ah[2]=p[4]; ah[3]=p[8*AP+4];
                const uint32_t* q2 = sQl + mRow*AP + ks*8 + t4;
                al[0]=q2[0]; al[1]=q2[8*AP]; al[2]=q2[4]; al[3]=q2[8*AP+4];
            }
            #pragma unroll
            for (int nt = 0; nt < 8; nt++) {
                uint32_t bh[2], bl[2];
                const uint32_t* p = sKh + (nt*8 + g)*AP + ks*8 + t4;
                bh[0] = p[0]; bh[1] = p[4];
                const uint32_t* q2 = sKl + (nt*8 + g)*AP + ks*8 + t4;
                bl[0] = q2[0]; bl[1] = q2[4];
                mma_tf32(s[nt], ah, bh);
                mma_tf32(s[nt], ah, bl);
                mma_tf32(s[nt], al, bh);
            }
        }

        if (kt == qt) {
            #pragma unroll
            for (int nt = 0; nt < 8; nt++) {
                int c0 = nt*8 + 2*t4;
                if (c0     > mRow)   s[nt][0] = -1e30f;
                if (c0 + 1 > mRow)   s[nt][1] = -1e30f;
                if (c0     > mRow+8) s[nt][2] = -1e30f;
                if (c0 + 1 > mRow+8) s[nt][3] = -1e30f;
            }
        }

        float rma = -1e30f, rmb = -1e30f;
        #pragma unroll
        for (int nt = 0; nt < 8; nt++) {
            rma = fmaxf(rma, fmaxf(s[nt][0], s[nt][1]));
            rmb = fmaxf(rmb, fmaxf(s[nt][2], s[nt][3]));
        }
        rma = fmaxf(rma, __shfl_xor_sync(0xffffffffu, rma, 1));
        rma = fmaxf(rma, __shfl_xor_sync(0xffffffffu, rma, 2));
        rmb = fmaxf(rmb, __shfl_xor_sync(0xffffffffu, rmb, 1));
        rmb = fmaxf(rmb, __shfl_xor_sync(0xffffffffu, rmb, 2));

        float mna = fmaxf(m_a, rma), mnb = fmaxf(m_b, rmb);
        float suma = 0.f, sumb = 0.f;
        #pragma unroll
        for (int nt = 0; nt < 8; nt++) {
            s[nt][0] = __expf(s[nt][0] - mna); suma += s[nt][0];
            s[nt][1] = __expf(s[nt][1] - mna); suma += s[nt][1];
            s[nt][2] = __expf(s[nt][2] - mnb); sumb += s[nt][2];
            s[nt][3] = __expf(s[nt][3] - mnb); sumb += s[nt][3];
        }
        suma += __shfl_xor_sync(0xffffffffu, suma, 1);
        suma += __shfl_xor_sync(0xffffffffu, suma, 2);
        sumb += __shfl_xor_sync(0xffffffffu, sumb, 1);
        sumb += __shfl_xor_sync(0xffffffffu, sumb, 2);

        float alpa = __expf(m_a - mna), alpb = __expf(m_b - mnb);
        l_a = l_a*alpa + suma; m_a = mna;
        l_b = l_b*alpb + sumb; m_b = mnb;
        #pragma unroll
        for (int nt = 0; nt < 8; nt++) {
            o[nt][0] *= alpa; o[nt][1] *= alpa;
            o[nt][2] *= alpb; o[nt][3] *= alpb;
        }

        #pragma unroll
        for (int nt = 0; nt < 8; nt++) {
            int c0 = nt*8 + 2*t4;
            sP[mRow*AP + c0]       = f2tf(s[nt][0]);
            sP[mRow*AP + c0 + 1]   = f2tf(s[nt][1]);
            sP[(mRow+8)*AP + c0]   = f2tf(s[nt][2]);
            sP[(mRow+8)*AP + c0+1] = f2tf(s[nt][3]);
        }
        __syncwarp();

        #pragma unroll
        for (int ks = 0; ks < 8; ks++) {
            uint32_t ap[4];
            const uint32_t* p = sP + mRow*AP + ks*8 + t4;
            ap[0]=p[0]; ap[1]=p[8*AP]; ap[2]=p[4]; ap[3]=p[8*AP+4];
            #pragma unroll
            for (int nt = 0; nt < 8; nt++) {
                uint32_t bv[2];
                bv[0] = sV[(ks*8 + t4)*AP + nt*8 + g];
                bv[1] = sV[(ks*8 + t4 + 4)*AP + nt*8 + g];
                mma_tf32(o[nt], ap, bv);
            }
        }
    }

    float inva = 1.f / l_a, invb = 1.f / l_b;
    #pragma unroll
    for (int nt = 0; nt < 8; nt++) {
        int col = h*HD + nt*8 + 2*t4;
        long ra = (long)(qt*64 + mRow);
        *(float2*)(attn + ra*H + col)     = make_float2(o[nt][0]*inva, o[nt][1]*inva);
        *(float2*)(attn + (ra+8)*H + col) = make_float2(o[nt][2]*invb, o[nt][3]*invb);
    }
}

// ---------------- router / MoE plumbing ---------------------------------------
__global__ void reset_kernel() { if (threadIdx.x < NE) g_counts[threadIdx.x] = 0; }

__global__ __launch_bounds__(256) void router_kernel(
    const float* __restrict__ x, const float* __restrict__ gw)
{
    int t = blockIdx.x;
    const float* xr = x + (long)t*H;
    float p[NE] = {};
    for (int h = threadIdx.x; h < H; h += 256) {
        float xv = xr[h];
        #pragma unroll
        for (int e = 0; e < NE; e++) p[e] += xv * gw[h*NE + e];
    }
    __shared__ float red[NE*256];
    #pragma unroll
    for (int e = 0; e < NE; e++) red[e*256 + threadIdx.x] = p[e];
    __syncthreads();
    for (int st = 128; st > 0; st >>= 1) {
        if (threadIdx.x < st)
            #pragma unroll
            for (int e = 0; e < NE; e++)
                red[e*256+threadIdx.x] += red[e*256+threadIdx.x+st];
        __syncthreads();
    }
    if (threadIdx.x == 0) {
        float l[NE];
        #pragma unroll
        for (int e = 0; e < NE; e++) l[e] = red[e*256];
        int i1 = 0;
        #pragma unroll
        for (int e = 1; e < NE; e++) if (l[e] > l[i1]) i1 = e;
        int i2 = -1;
        #pragma unroll
        for (int e = 0; e < NE; e++) if (e != i1 && (i2 < 0 || l[e] > l[i2])) i2 = e;
        float p2 = expf(l[i2] - l[i1]);
        float inv = 1.f / (1.f + p2);
        g_topid[2*t] = i1;   g_topid[2*t+1] = i2;
        g_topw[2*t]  = inv;  g_topw[2*t+1]  = p2*inv;
        atomicAdd(&g_counts[i1], 1);
        atomicAdd(&g_counts[i2], 1);
    }
}

__global__ void scan_kernel() {
    if (threadIdx.x == 0) {
        int s = 0;
        for (int e = 0; e < NE; e++) { g_offs[e] = s; g_fill[e] = s; s += g_counts[e]; }
    }
}

__global__ void scatter_kernel() {
    int t = blockIdx.x*256 + threadIdx.x;
    if (t >= T) return;
    #pragma unroll
    for (int k = 0; k < 2; k++) {
        int e = g_topid[2*t+k];
        int pos = atomicAdd(&g_fill[e], 1);
        g_perm[pos]  = t;
        g_permw[pos] = g_topw[2*t+k];
        g_tokpos[2*t+k] = pos;
    }
}

__global__ __launch_bounds__(256) void silu_kernel() {
    long n = (long)ASSIGN*FFN;
    for (long i = (long)blockIdx.x*256 + threadIdx.x; i < n; i += (long)gridDim.x*256) {
        float a = g_h1[i];
        g_h1[i] = (a / (1.f + expf(-a))) * g_h3[i];
    }
}

__global__ __launch_bounds__(256) void combine_kernel(float* __restrict__ out) {
    int idx = blockIdx.x*256 + threadIdx.x;
    int t = idx >> 11;
    int c = idx & (H-1);
    out[idx] = g_y[(long)g_tokpos[2*t]*H + c] + g_y[(long)g_tokpos[2*t+1]*H + c];
}

// ---------------- launch --------------------------------------------------------
extern "C" void kernel_launch(void* const* d_in, const int* in_sizes, int n_in,
                              void* d_out, int out_size)
{
    const float* hidden = (const float*)d_in[0];
    const float* w_qkv  = (const float*)d_in[2];
    const float* w_o    = (const float*)d_in[3];
    const float* gate_w = (const float*)d_in[4];
    const float* w1     = (const float*)d_in[5];
    const float* w2     = (const float*)d_in[6];
    const float* w3     = (const float*)d_in[7];
    const float* ln1    = (const float*)d_in[8];
    const float* ln2    = (const float*)d_in[9];

    float* out       = (float*)d_out;
    float* final_out = out;
    float* resid_out = out + (long)T*H;

    float *xnorm, *qkvb, *attnb, *x2, *h1, *h3, *y;
    cudaGetSymbolAddress((void**)&xnorm, g_xnorm);
    cudaGetSymbolAddress((void**)&qkvb,  g_qkv);
    cudaGetSymbolAddress((void**)&attnb, g_attn);
    cudaGetSymbolAddress((void**)&x2,    g_x2);
    cudaGetSymbolAddress((void**)&h1,    g_h1);
    cudaGetSymbolAddress((void**)&h3,    g_h3);
    cudaGetSymbolAddress((void**)&y,     g_y);

    static bool attrDone = false;
    if (!attrDone) {
        cudaFuncSetAttribute(gemm9<0>, cudaFuncAttributeMaxDynamicSharedMemorySize, G9_SMEM);
        cudaFuncSetAttribute(gemm9<1>, cudaFuncAttributeMaxDynamicSharedMemorySize, G9_SMEM);
        cudaFuncSetAttribute(gemm9<2>, cudaFuncAttributeMaxDynamicSharedMemorySize, G9_SMEM);
        cudaFuncSetAttribute(attn_tc_kernel, cudaFuncAttributeMaxDynamicSharedMemorySize, ATTN_SMEM);
        attrDone = true;
    }

    // ---- attention path ----
    rmsnorm_kernel<<<T,256>>>(hidden, ln1, xnorm);
    {
        dim3 g(QKV_N/256, T/128, 1);
        gemm9<0><<<g,256,G9_SMEM>>>(xnorm, w_qkv, qkvb, T, QKV_N, H, nullptr, 0);
    }
    rope_kernel<<<T,256>>>(qkvb);
    {
        dim3 g(T/64, NH, 1);
        attn_tc_kernel<<<g,128,ATTN_SMEM>>>(qkvb, attnb);
    }
    {
        dim3 g(H/256, T/128, 1);
        gemm9<0><<<g,256,G9_SMEM>>>(attnb, w_o, resid_out, T, H, H, hidden, 0);
    }

    // ---- MoE path ----
    rmsnorm_kernel<<<T,256>>>(resid_out, ln2, x2);
    reset_kernel<<<1,32>>>();
    router_kernel<<<T,256>>>(x2, gate_w);
    scan_kernel<<<1,1>>>();
    scatter_kernel<<<(T+255)/256,256>>>();
    {
        dim3 g(FFN/256, T/128, NE);
        gemm9<1><<<g,256,G9_SMEM>>>(x2, w1, h1, T, FFN, H, nullptr, (long)H*FFN);
        gemm9<1><<<g,256,G9_SMEM>>>(x2, w3, h3, T, FFN, H, nullptr, (long)H*FFN);
    }
    silu_kernel<<<4096,256>>>();
    {
        dim3 g(H/256, T/128, NE);
        gemm9<2><<<g,256,G9_SMEM>>>(h1, w2, y, T, H, FFN, nullptr, (long)FFN*H);
    }
    combine_kernel<<<(T*H)/256,256>>>(final_out);
}

// round 10
// speedup vs baseline: 1.3627x; 1.0596x over previous
#include <cuda_runtime.h>
#include <cuda_fp16.h>
#include <math.h>
#include <stdint.h>

#define T 2048
#define H 2048
#define NH 32
#define NKV 8
#define HD 64
#define FFN 4096
#define NE 8
#define QKV_N 3072
#define ASSIGN (2*T)

// ---------------- scratch ----------------------------------------------------
__device__ float g_xnorm[T*H];
__device__ float g_qkv[(long)T*QKV_N];
__device__ float g_attn[(long)T*H];
__device__ float g_x2[(long)T*H];
__device__ float g_h1[(long)ASSIGN*FFN];
__device__ float g_h3[(long)ASSIGN*FFN];
__device__ float g_y[(long)ASSIGN*H];
__device__ int   g_counts[NE];
__device__ int   g_offs[NE];
__device__ int   g_fill[NE];
__device__ int   g_perm[ASSIGN];
__device__ float g_permw[ASSIGN];
__device__ int   g_tokpos[ASSIGN];
__device__ int   g_topid[T*2];
__device__ float g_topw[T*2];

// ---------------- helpers ------------------------------------------------------
__device__ __forceinline__ uint32_t f2tf(float f) {
    uint32_t u; asm("cvt.rna.tf32.f32 %0, %1;" : "=r"(u) : "f"(f)); return u;
}
__device__ __forceinline__ void mma_tf32(float* c, const uint32_t* a, const uint32_t* b) {
    asm volatile(
        "mma.sync.aligned.m16n8k8.row.col.f32.tf32.tf32.f32 "
        "{%0,%1,%2,%3},{%4,%5,%6,%7},{%8,%9},{%0,%1,%2,%3};"
        : "+f"(c[0]), "+f"(c[1]), "+f"(c[2]), "+f"(c[3])
        : "r"(a[0]), "r"(a[1]), "r"(a[2]), "r"(a[3]), "r"(b[0]), "r"(b[1]));
}
__device__ __forceinline__ void mma_f16(float* c, const uint32_t* a, const uint32_t* b) {
    asm volatile(
        "mma.sync.aligned.m16n8k16.row.col.f32.f16.f16.f32 "
        "{%0,%1,%2,%3},{%4,%5,%6,%7},{%8,%9},{%0,%1,%2,%3};"
        : "+f"(c[0]), "+f"(c[1]), "+f"(c[2]), "+f"(c[3])
        : "r"(a[0]), "r"(a[1]), "r"(a[2]), "r"(a[3]), "r"(b[0]), "r"(b[1]));
}
__device__ __forceinline__ uint32_t packh2(float lo, float hi) {
    __half2 h = __floats2half2_rn(lo, hi);
    return *(uint32_t*)&h;
}
__device__ __forceinline__ uint32_t smem_u32(const void* p) {
    uint32_t a;
    asm("{ .reg .u64 t; cvta.to.shared.u64 t, %1; cvt.u32.u64 %0, t; }" : "=r"(a) : "l"(p));
    return a;
}

// ---------------- rmsnorm ------------------------------------------------------
__global__ __launch_bounds__(256) void rmsnorm_kernel(
    const float* __restrict__ x, const float* __restrict__ w, float* __restrict__ out)
{
    int t = blockIdx.x;
    const float* xr = x + (long)t*H;
    __shared__ float red[256];
    float s = 0.f;
    for (int h = threadIdx.x; h < H; h += 256) { float v = xr[h]; s += v*v; }
    red[threadIdx.x] = s; __syncthreads();
    for (int st = 128; st > 0; st >>= 1) {
        if (threadIdx.x < st) red[threadIdx.x] += red[threadIdx.x+st];
        __syncthreads();
    }
    float inv = rsqrtf(red[0]/(float)H + 1e-5f);
    float* orow = out + (long)t*H;
    for (int h = threadIdx.x; h < H; h += 256) orow[h] = xr[h]*inv*w[h];
}

// ---------------- fp16 mma.sync GEMM: 128x256 CTA, 64x64 warp tiles ------------
#define PAW 18
#define PBW 18
#define A9_WORDS (128*PAW)
#define B9_WORDS (256*PBW)
#define G9_SMEM ((2*(A9_WORDS+B9_WORDS))*4)

template<int MODE>
__global__ __launch_bounds__(256) void gemm9(
    const float* __restrict__ A, const float* __restrict__ B, float* __restrict__ C,
    int M, int N, int K, const float* __restrict__ addsrc, long bStrideZ)
{
    extern __shared__ uint32_t sm9[];
    int z = blockIdx.z;
    int mBase = blockIdx.y * 128;
    int nBase = blockIdx.x * 256;
    int Meff = M, rowOff = 0;
    if (MODE == 1 || MODE == 2) {
        Meff = g_counts[z]; rowOff = g_offs[z];
        if (mBase >= Meff) return;
        B += (long)z * bStrideZ;
    }

    int tid = threadIdx.x, lane = tid & 31, wid = tid >> 5;
    int mW = (wid >> 2) * 64;
    int nW = (wid & 3) * 64;
    int g  = lane >> 2, t4 = lane & 3;

    uint32_t* smA = sm9;
    uint32_t* smB = sm9 + 2*A9_WORDS;

    int arow = tid >> 3;
    int ac   = tid & 7;
    const float* aPtr[4]; bool aOk[4];
    #pragma unroll
    for (int i = 0; i < 4; i++) {
        int gm = mBase + arow + 32*i;
        aOk[i] = gm < Meff;
        long r;
        if (MODE == 1)      r = aOk[i] ? (long)g_perm[rowOff + gm] : 0;
        else if (MODE == 2) r = (long)(rowOff + (aOk[i] ? gm : 0));
        else                r = (long)(aOk[i] ? gm : 0);
        aPtr[i] = A + r*(long)K + ac*4;
    }
    int nl = tid & 63;
    int kp = tid >> 6;
    const float* bPtr = B + nBase + nl;

    float acc[4][8][4];
    #pragma unroll
    for (int mt = 0; mt < 4; mt++)
        #pragma unroll
        for (int nt = 0; nt < 8; nt++)
            #pragma unroll
            for (int q = 0; q < 4; q++) acc[mt][nt][q] = 0.f;

    int KT = K >> 5;
    float4 aR[4];
    float bv0[4][4], bv1[4][4];

    #pragma unroll
    for (int i = 0; i < 4; i++)
        aR[i] = aOk[i] ? *(const float4*)(aPtr[i]) : make_float4(0.f,0.f,0.f,0.f);
    #pragma unroll
    for (int p = 0; p < 4; p++)
        #pragma unroll
        for (int j = 0; j < 4; j++) {
            long ko = (long)(2*(kp + 4*p))*N + 64*j;
            bv0[p][j] = bPtr[ko];
            bv1[p][j] = bPtr[ko + N];
        }
    #pragma unroll
    for (int i = 0; i < 4; i++) {
        uint2 u = { packh2(aR[i].x, aR[i].y), packh2(aR[i].z, aR[i].w) };
        *(uint2*)(smA + (arow + 32*i)*PAW + ac*2) = u;
    }
    #pragma unroll
    for (int p = 0; p < 4; p++)
        #pragma unroll
        for (int j = 0; j < 4; j++)
            smB[(nl + 64*j)*PBW + kp + 4*p] = packh2(bv0[p][j], bv1[p][j]);
    __syncthreads();

    for (int kt = 0; kt < KT; kt++) {
        int buf = kt & 1;
        int nb  = buf ^ 1;
        if (kt + 1 < KT) {
            int k0 = (kt + 1) << 5;
            #pragma unroll
            for (int i = 0; i < 4; i++)
                aR[i] = aOk[i] ? *(const float4*)(aPtr[i] + k0)
                               : make_float4(0.f,0.f,0.f,0.f);
            #pragma unroll
            for (int p = 0; p < 4; p++)
                #pragma unroll
                for (int j = 0; j < 4; j++) {
                    long ko = (long)(k0 + 2*(kp + 4*p))*N + 64*j;
                    bv0[p][j] = bPtr[ko];
                    bv1[p][j] = bPtr[ko + N];
                }
        }

        const uint32_t* as = smA + buf*A9_WORDS;
        const uint32_t* bs = smB + buf*B9_WORDS;

        #pragma unroll
        for (int s = 0; s < 2; s++) {
            uint32_t af[4][4], bf[8][2];
            #pragma unroll
            for (int mt = 0; mt < 4; mt++) {
                const uint32_t* p = as + (mW + mt*16 + g)*PAW + s*8 + t4;
                af[mt][0] = p[0];
                af[mt][1] = p[8*PAW];
                af[mt][2] = p[4];
                af[mt][3] = p[8*PAW + 4];
            }
            #pragma unroll
            for (int nt = 0; nt < 8; nt++) {
                const uint32_t* p = bs + (nW + nt*8 + g)*PBW + s*8 + t4;
                bf[nt][0] = p[0];
                bf[nt][1] = p[4];
            }
            #pragma unroll
            for (int mt = 0; mt < 4; mt++)
                #pragma unroll
                for (int nt = 0; nt < 8; nt++)
                    mma_f16(acc[mt][nt], af[mt], bf[nt]);
        }

        if (kt + 1 < KT) {
            uint32_t* dA = smA + nb*A9_WORDS;
            uint32_t* dB = smB + nb*B9_WORDS;
            #pragma unroll
            for (int i = 0; i < 4; i++) {
                uint2 u = { packh2(aR[i].x, aR[i].y), packh2(aR[i].z, aR[i].w) };
                *(uint2*)(dA + (arow + 32*i)*PAW + ac*2) = u;
            }
            #pragma unroll
            for (int p = 0; p < 4; p++)
                #pragma unroll
                for (int j = 0; j < 4; j++)
                    dB[(nl + 64*j)*PBW + kp + 4*p] = packh2(bv0[p][j], bv1[p][j]);
        }
        __syncthreads();
    }

    #pragma unroll
    for (int mt = 0; mt < 4; mt++) {
        #pragma unroll
        for (int half = 0; half < 2; half++) {
            int rRel = mW + mt*16 + g + half*8;
            bool ok = (MODE == 0) || (mBase + rRel < Meff);
            if (!ok) continue;
            long crow;
            float scale = 1.f;
            if (MODE == 0) crow = (long)(mBase + rRel);
            else           crow = (long)(rowOff + mBase + rRel);
            if (MODE == 2) scale = g_permw[rowOff + mBase + rRel];
            #pragma unroll
            for (int nt = 0; nt < 8; nt++) {
                int col = nBase + nW + nt*8 + t4*2;
                float v0 = acc[mt][nt][2*half + 0];
                float v1 = acc[mt][nt][2*half + 1];
                if (MODE == 2) { v0 *= scale; v1 *= scale; }
                if (MODE == 0 && addsrc) {
                    v0 += addsrc[crow*N + col];
                    v1 += addsrc[crow*N + col + 1];
                }
                *(float2*)(C + crow*N + col) = make_float2(v0, v1);
            }
        }
    }
}

// ---------------- RoPE --------------------------------------------------------
__global__ __launch_bounds__(256) void rope_kernel(float* __restrict__ qkv)
{
    int t = blockIdx.x;
    float pos = (float)t;
    for (int idx = threadIdx.x; idx < (NH+NKV)*32; idx += 256) {
        int head = idx >> 5;
        int j    = idx & 31;
        int colbase = (head < NH) ? head*HD : (NH*HD + (head-NH)*HD);
        float inv = expf(-((float)(2*j)/(float)HD) * logf(10000.0f));
        float f = pos * inv;
        float c = cosf(f), sn = sinf(f);
        float* p = qkv + (long)t*QKV_N + colbase;
        float x1 = p[j], x2 = p[j+32];
        p[j]    = x1*c - x2*sn;
        p[j+32] = x2*c + x1*sn;
    }
}

// ---------------- flash attention: split-fp16 QK^T, tf32 PV --------------------
// 4 warps x 16 q-rows. Q/K stored as packed half2 [row][k-pair], pitch PH words.
// V, P stored fp32/tf32 at pitch AP (as before). 3 CTAs/SM.
#define PH 36
#define AP 68
#define ATTN_SMEM ((4*64*PH + 2*64*AP)*4)

__global__ __launch_bounds__(128) void attn_tc_kernel(
    const float* __restrict__ qkv, float* __restrict__ attn)
{
    extern __shared__ uint32_t su[];
    uint32_t* sQh = su;
    uint32_t* sQl = sQh + 64*PH;
    uint32_t* sKh = sQl + 64*PH;
    uint32_t* sKl = sKh + 64*PH;
    uint32_t* sV  = sKl + 64*PH;
    uint32_t* sP  = sV  + 64*AP;

    int h = blockIdx.y, qt = blockIdx.x;
    int kvh = h >> 2;
    int tid = threadIdx.x, lane = tid & 31, w = tid >> 5;
    int g = lane >> 2, t4 = lane & 3;
    int mRow = w*16 + g;

    // ---- load Q (scaled), split into fp16 hi/lo, packed pairs ----
    for (int i = tid; i < 1024; i += 128) {
        int r = i >> 4, d4 = (i & 15) << 2;
        float4 v = *(const float4*)(qkv + (long)(qt*64 + r)*QKV_N + h*HD + d4);
        float q0 = v.x*0.125f, q1 = v.y*0.125f, q2 = v.z*0.125f, q3 = v.w*0.125f;
        __half h0 = __float2half_rn(q0), h1 = __float2half_rn(q1);
        __half h2 = __float2half_rn(q2), h3 = __float2half_rn(q3);
        float l0 = q0 - __half2float(h0), l1 = q1 - __half2float(h1);
        float l2 = q2 - __half2float(h2), l3 = q3 - __half2float(h3);
        __half2 p0 = __halves2half2(h0, h1), p1 = __halves2half2(h2, h3);
        uint2 uh = { *(uint32_t*)&p0, *(uint32_t*)&p1 };
        uint2 ul = { packh2(l0, l1), packh2(l2, l3) };
        *(uint2*)(sQh + r*PH + (d4 >> 1)) = uh;
        *(uint2*)(sQl + r*PH + (d4 >> 1)) = ul;
    }

    float m_a = -1e30f, m_b = -1e30f, l_a = 0.f, l_b = 0.f;
    float o[8][4];
    #pragma unroll
    for (int nt = 0; nt < 8; nt++)
        #pragma unroll
        for (int q = 0; q < 4; q++) o[nt][q] = 0.f;

    for (int kt = 0; kt <= qt; kt++) {
        __syncthreads();
        for (int i = tid; i < 1024; i += 128) {
            int r = i >> 4, d4 = (i & 15) << 2;
            const float* kp = qkv + (long)(kt*64 + r)*QKV_N + NH*HD + kvh*HD + d4;
            float4 kv = *(const float4*)kp;
            float4 vv = *(const float4*)(kp + NKV*HD);
            __half h0 = __float2half_rn(kv.x), h1 = __float2half_rn(kv.y);
            __half h2 = __float2half_rn(kv.z), h3 = __float2half_rn(kv.w);
            float l0 = kv.x - __half2float(h0), l1 = kv.y - __half2float(h1);
            float l2 = kv.z - __half2float(h2), l3 = kv.w - __half2float(h3);
            __half2 p0 = __halves2half2(h0, h1), p1 = __halves2half2(h2, h3);
            uint2 uh = { *(uint32_t*)&p0, *(uint32_t*)&p1 };
            uint2 ul = { packh2(l0, l1), packh2(l2, l3) };
            *(uint2*)(sKh + r*PH + (d4 >> 1)) = uh;
            *(uint2*)(sKl + r*PH + (d4 >> 1)) = ul;
            sV[r*AP + d4 + 0] = f2tf(vv.x);
            sV[r*AP + d4 + 1] = f2tf(vv.y);
            sV[r*AP + d4 + 2] = f2tf(vv.z);
            sV[r*AP + d4 + 3] = f2tf(vv.w);
        }
        __syncthreads();

        // ---- S = Q K^T : split-fp16, 4 steps of k16 ----
        float s[8][4];
        #pragma unroll
        for (int nt = 0; nt < 8; nt++)
            #pragma unroll
            for (int q = 0; q < 4; q++) s[nt][q] = 0.f;

        #pragma unroll
        for (int ks = 0; ks < 4; ks++) {
            uint32_t ah[4], al[4];
            {
                const uint32_t* p = sQh + mRow*PH + ks*8 + t4;
                ah[0]=p[0]; ah[1]=p[8*PH]; ah[2]=p[4]; ah[3]=p[8*PH+4];
                const uint32_t* q2 = sQl + mRow*PH + ks*8 + t4;
                al[0]=q2[0]; al[1]=q2[8*PH]; al[2]=q2[4]; al[3]=q2[8*PH+4];
            }
            #pragma unroll
            for (int nt = 0; nt < 8; nt++) {
                uint32_t bh[2], bl[2];
                const uint32_t* p = sKh + (nt*8 + g)*PH + ks*8 + t4;
                bh[0] = p[0]; bh[1] = p[4];
                const uint32_t* q2 = sKl + (nt*8 + g)*PH + ks*8 + t4;
                bl[0] = q2[0]; bl[1] = q2[4];
                mma_f16(s[nt], ah, bh);
                mma_f16(s[nt], ah, bl);
                mma_f16(s[nt], al, bh);
            }
        }

        if (kt == qt) {
            #pragma unroll
            for (int nt = 0; nt < 8; nt++) {
                int c0 = nt*8 + 2*t4;
                if (c0     > mRow)   s[nt][0] = -1e30f;
                if (c0 + 1 > mRow)   s[nt][1] = -1e30f;
                if (c0     > mRow+8) s[nt][2] = -1e30f;
                if (c0 + 1 > mRow+8) s[nt][3] = -1e30f;
            }
        }

        float rma = -1e30f, rmb = -1e30f;
        #pragma unroll
        for (int nt = 0; nt < 8; nt++) {
            rma = fmaxf(rma, fmaxf(s[nt][0], s[nt][1]));
            rmb = fmaxf(rmb, fmaxf(s[nt][2], s[nt][3]));
        }
        rma = fmaxf(rma, __shfl_xor_sync(0xffffffffu, rma, 1));
        rma = fmaxf(rma, __shfl_xor_sync(0xffffffffu, rma, 2));
        rmb = fmaxf(rmb, __shfl_xor_sync(0xffffffffu, rmb, 1));
        rmb = fmaxf(rmb, __shfl_xor_sync(0xffffffffu, rmb, 2));

        float mna = fmaxf(m_a, rma), mnb = fmaxf(m_b, rmb);
        float suma = 0.f, sumb = 0.f;
        #pragma unroll
        for (int nt = 0; nt < 8; nt++) {
            s[nt][0] = __expf(s[nt][0] - mna); suma += s[nt][0];
            s[nt][1] = __expf(s[nt][1] - mna); suma += s[nt][1];
            s[nt][2] = __expf(s[nt][2] - mnb); sumb += s[nt][2];
            s[nt][3] = __expf(s[nt][3] - mnb); sumb += s[nt][3];
        }
        suma += __shfl_xor_sync(0xffffffffu, suma, 1);
        suma += __shfl_xor_sync(0xffffffffu, suma, 2);
        sumb += __shfl_xor_sync(0xffffffffu, sumb, 1);
        sumb += __shfl_xor_sync(0xffffffffu, sumb, 2);

        float alpa = __expf(m_a - mna), alpb = __expf(m_b - mnb);
        l_a = l_a*alpa + suma; m_a = mna;
        l_b = l_b*alpb + sumb; m_b = mnb;
        #pragma unroll
        for (int nt = 0; nt < 8; nt++) {
            o[nt][0] *= alpa; o[nt][1] *= alpa;
            o[nt][2] *= alpb; o[nt][3] *= alpb;
        }

        // ---- write P (warp-private rows), tf32 ----
        #pragma unroll
        for (int nt = 0; nt < 8; nt++) {
            int c0 = nt*8 + 2*t4;
            sP[mRow*AP + c0]       = f2tf(s[nt][0]);
            sP[mRow*AP + c0 + 1]   = f2tf(s[nt][1]);
            sP[(mRow+8)*AP + c0]   = f2tf(s[nt][2]);
            sP[(mRow+8)*AP + c0+1] = f2tf(s[nt][3]);
        }
        __syncwarp();

        // ---- O += P V (tf32, unchanged) ----
        #pragma unroll
        for (int ks = 0; ks < 8; ks++) {
            uint32_t ap[4];
            const uint32_t* p = sP + mRow*AP + ks*8 + t4;
            ap[0]=p[0]; ap[1]=p[8*AP]; ap[2]=p[4]; ap[3]=p[8*AP+4];
            #pragma unroll
            for (int nt = 0; nt < 8; nt++) {
                uint32_t bv[2];
                bv[0] = sV[(ks*8 + t4)*AP + nt*8 + g];
                bv[1] = sV[(ks*8 + t4 + 4)*AP + nt*8 + g];
                mma_tf32(o[nt], ap, bv);
            }
        }
    }

    float inva = 1.f / l_a, invb = 1.f / l_b;
    #pragma unroll
    for (int nt = 0; nt < 8; nt++) {
        int col = h*HD + nt*8 + 2*t4;
        long ra = (long)(qt*64 + mRow);
        *(float2*)(attn + ra*H + col)     = make_float2(o[nt][0]*inva, o[nt][1]*inva);
        *(float2*)(attn + (ra+8)*H + col) = make_float2(o[nt][2]*invb, o[nt][3]*invb);
    }
}

// ---------------- router / MoE plumbing ---------------------------------------
__global__ void reset_kernel() { if (threadIdx.x < NE) g_counts[threadIdx.x] = 0; }

__global__ __launch_bounds__(256) void router_kernel(
    const float* __restrict__ x, const float* __restrict__ gw)
{
    int t = blockIdx.x;
    const float* xr = x + (long)t*H;
    float p[NE] = {};
    for (int h = threadIdx.x; h < H; h += 256) {
        float xv = xr[h];
        #pragma unroll
        for (int e = 0; e < NE; e++) p[e] += xv * gw[h*NE + e];
    }
    __shared__ float red[NE*256];
    #pragma unroll
    for (int e = 0; e < NE; e++) red[e*256 + threadIdx.x] = p[e];
    __syncthreads();
    for (int st = 128; st > 0; st >>= 1) {
        if (threadIdx.x < st)
            #pragma unroll
            for (int e = 0; e < NE; e++)
                red[e*256+threadIdx.x] += red[e*256+threadIdx.x+st];
        __syncthreads();
    }
    if (threadIdx.x == 0) {
        float l[NE];
        #pragma unroll
        for (int e = 0; e < NE; e++) l[e] = red[e*256];
        int i1 = 0;
        #pragma unroll
        for (int e = 1; e < NE; e++) if (l[e] > l[i1]) i1 = e;
        int i2 = -1;
        #pragma unroll
        for (int e = 0; e < NE; e++) if (e != i1 && (i2 < 0 || l[e] > l[i2])) i2 = e;
        float p2 = expf(l[i2] - l[i1]);
        float inv = 1.f / (1.f + p2);
        g_topid[2*t] = i1;   g_topid[2*t+1] = i2;
        g_topw[2*t]  = inv;  g_topw[2*t+1]  = p2*inv;
        atomicAdd(&g_counts[i1], 1);
        atomicAdd(&g_counts[i2], 1);
    }
}

__global__ void scan_kernel() {
    if (threadIdx.x == 0) {
        int s = 0;
        for (int e = 0; e < NE; e++) { g_offs[e] = s; g_fill[e] = s; s += g_counts[e]; }
    }
}

__global__ void scatter_kernel() {
    int t = blockIdx.x*256 + threadIdx.x;
    if (t >= T) return;
    #pragma unroll
    for (int k = 0; k < 2; k++) {
        int e = g_topid[2*t+k];
        int pos = atomicAdd(&g_fill[e], 1);
        g_perm[pos]  = t;
        g_permw[pos] = g_topw[2*t+k];
        g_tokpos[2*t+k] = pos;
    }
}

__global__ __launch_bounds__(256) void silu_kernel() {
    long n = (long)ASSIGN*FFN;
    for (long i = (long)blockIdx.x*256 + threadIdx.x; i < n; i += (long)gridDim.x*256) {
        float a = g_h1[i];
        g_h1[i] = (a / (1.f + expf(-a))) * g_h3[i];
    }
}

__global__ __launch_bounds__(256) void combine_kernel(float* __restrict__ out) {
    int idx = blockIdx.x*256 + threadIdx.x;
    int t = idx >> 11;
    int c = idx & (H-1);
    out[idx] = g_y[(long)g_tokpos[2*t]*H + c] + g_y[(long)g_tokpos[2*t+1]*H + c];
}

// ---------------- launch --------------------------------------------------------
extern "C" void kernel_launch(void* const* d_in, const int* in_sizes, int n_in,
                              void* d_out, int out_size)
{
    const float* hidden = (const float*)d_in[0];
    const float* w_qkv  = (const float*)d_in[2];
    const float* w_o    = (const float*)d_in[3];
    const float* gate_w = (const float*)d_in[4];
    const float* w1     = (const float*)d_in[5];
    const float* w2     = (const float*)d_in[6];
    const float* w3     = (const float*)d_in[7];
    const float* ln1    = (const float*)d_in[8];
    const float* ln2    = (const float*)d_in[9];

    float* out       = (float*)d_out;
    float* final_out = out;
    float* resid_out = out + (long)T*H;

    float *xnorm, *qkvb, *attnb, *x2, *h1, *h3, *y;
    cudaGetSymbolAddress((void**)&xnorm, g_xnorm);
    cudaGetSymbolAddress((void**)&qkvb,  g_qkv);
    cudaGetSymbolAddress((void**)&attnb, g_attn);
    cudaGetSymbolAddress((void**)&x2,    g_x2);
    cudaGetSymbolAddress((void**)&h1,    g_h1);
    cudaGetSymbolAddress((void**)&h3,    g_h3);
    cudaGetSymbolAddress((void**)&y,     g_y);

    static bool attrDone = false;
    if (!attrDone) {
        cudaFuncSetAttribute(gemm9<0>, cudaFuncAttributeMaxDynamicSharedMemorySize, G9_SMEM);
        cudaFuncSetAttribute(gemm9<1>, cudaFuncAttributeMaxDynamicSharedMemorySize, G9_SMEM);
        cudaFuncSetAttribute(gemm9<2>, cudaFuncAttributeMaxDynamicSharedMemorySize, G9_SMEM);
        cudaFuncSetAttribute(attn_tc_kernel, cudaFuncAttributeMaxDynamicSharedMemorySize, ATTN_SMEM);
        attrDone = true;
    }

    // ---- attention path ----
    rmsnorm_kernel<<<T,256>>>(hidden, ln1, xnorm);
    {
        dim3 g(QKV_N/256, T/128, 1);
        gemm9<0><<<g,256,G9_SMEM>>>(xnorm, w_qkv, qkvb, T, QKV_N, H, nullptr, 0);
    }
    rope_kernel<<<T,256>>>(qkvb);
    {
        dim3 g(T/64, NH, 1);
        attn_tc_kernel<<<g,128,ATTN_SMEM>>>(qkvb, attnb);
    }
    {
        dim3 g(H/256, T/128, 1);
        gemm9<0><<<g,256,G9_SMEM>>>(attnb, w_o, resid_out, T, H, H, hidden, 0);
    }

    // ---- MoE path ----
    rmsnorm_kernel<<<T,256>>>(resid_out, ln2, x2);
    reset_kernel<<<1,32>>>();
    router_kernel<<<T,256>>>(x2, gate_w);
    scan_kernel<<<1,1>>>();
    scatter_kernel<<<(T+255)/256,256>>>();
    {
        dim3 g(FFN/256, T/128, NE);
        gemm9<1><<<g,256,G9_SMEM>>>(x2, w1, h1, T, FFN, H, nullptr, (long)H*FFN);
        gemm9<1><<<g,256,G9_SMEM>>>(x2, w3, h3, T, FFN, H, nullptr, (long)H*FFN);
    }
    silu_kernel<<<4096,256>>>();
    {
        dim3 g(H/256, T/128, NE);
        gemm9<2><<<g,256,G9_SMEM>>>(h1, w2, y, T, H, FFN, nullptr, (long)FFN*H);
    }
    combine_kernel<<<(T*H)/256,256>>>(final_out);
}